// round 3
// baseline (speedup 1.0000x reference)
#include <cuda_runtime.h>
#include <math.h>

#define HW     16384
#define NCH    512
#define NC     16       // classes per group (C)
#define NG     32       // groups (G)
#define NB     8        // batch
#define NPAIR  120      // C*(C-1)/2
#define NBG    256      // NB*NG
#define QTR    4096     // floats per channel per quarter of HW
#define TILE   256      // floats per channel per pipeline tile
#define NT     (QTR / TILE)     // 16 tiles per quarter
#define STAGES 6
#define DEPTH  4                // tiles in flight
#define STAGE_FLOATS (NC * TILE)            // 4096 floats = 16 KB
#define SMEM_BYTES   (STAGES * STAGE_FLOATS * 4)   // 96 KB dynamic

// Device-global scratch (no allocations allowed)
__device__ int   g_chan[NG][NC];          // channel id: rank-g pick of class c
__device__ float g_wgt[NG][NC];           // sigmoid(|w|) of that pick
__device__ float g_S4[NBG][4][NPAIR];     // per-quarter raw Gram partials

// ---------------------------------------------------------------------------
// Kernel A: selection via rank counting.
// grid = (16 classes, 8 channel-chunks), 512 threads.
// Thread = (channel-in-chunk chl = tid>>3, compare-slice sl = tid&7);
// each slice does 64 comparisons; shfl-reduce the 8 slices (lane bits 0-2).
// rank(i) = #{k : w_k > w_i or (w_k == w_i and k < i)} -> stable argsort(-w).
// ---------------------------------------------------------------------------
__global__ void select_kernel(const float* __restrict__ cw) {
    __shared__ float sw[NCH];
    const int j   = blockIdx.x;          // class
    const int q   = blockIdx.y;          // channel chunk (8 x 64)
    const int tid = threadIdx.x;
    sw[tid] = fabsf(cw[j * NCH + tid]);
    __syncthreads();

    const int chl = tid >> 3;            // 0..63 channel-in-chunk
    const int sl  = tid & 7;             // compare slice
    const int i   = q * 64 + chl;        // global channel
    const float wi = sw[i];

    int r = 0;
    const int k0 = sl * 64;
    #pragma unroll 8
    for (int k = k0; k < k0 + 64; k++) {
        const float wk = sw[k];
        r += (wk > wi) || (wk == wi && k < i);
    }
    r += __shfl_xor_sync(0xffffffffu, r, 1);
    r += __shfl_xor_sync(0xffffffffu, r, 2);
    r += __shfl_xor_sync(0xffffffffu, r, 4);

    if (sl == 0 && r < NG) {
        g_chan[r][j] = i;
        g_wgt[r][j]  = 1.0f / (1.0f + expf(-wi));
    }
}

// ---------------------------------------------------------------------------
// Kernel B: Gram accumulation. 512 threads, 6-stage / depth-4 cp.async pipe.
// grid = 1024 blocks = (bg 0..255) x (quarter 0..3).
//   loader role:  warp mc (=tid>>5) feeds channel mc; lane ms copies 32 B
//                 (2 x cp.async.cg 16B) of that channel's 1 KB tile slice.
//   compute role: grp = tid>>8 picks pair-half [0,60)/[60,120);
//                 lt = tid&255 is the scalar float position in the tile.
// Registers: 60 acc + 16 scalar v ~= 85 (no spills, no float2 pressure).
// ---------------------------------------------------------------------------
template <int P0>
__device__ __forceinline__ void do_pairs(const float* __restrict__ v,
                                         float* __restrict__ acc) {
    int p = 0;
    #pragma unroll
    for (int c = 0; c < NC; c++) {
        #pragma unroll
        for (int d = c + 1; d < NC; d++) {
            if (p >= P0 && p < P0 + 60)
                acc[p - P0] = fmaf(v[c], v[d], acc[p - P0]);
            p++;
        }
    }
}

__global__ __launch_bounds__(512) void gram_kernel(const float* __restrict__ x) {
    extern __shared__ __align__(16) float s_buf[];   // [STAGES][NC][TILE]

    const int bid = blockIdx.x;
    const int q   = bid & 3;
    const int bg  = bid >> 2;
    const int b   = bg >> 5;
    const int g   = bg & 31;
    const int tid = threadIdx.x;

    // loader role: warp -> channel, lane -> 32B slot
    const int mc = tid >> 5;             // channel / warp id
    const int ms = tid & 31;             // lane: 2 consecutive float4 slots
    const float* src = x + ((size_t)(b * NCH + g_chan[g][mc])) * HW + q * QTR;

    // compute role
    const int grp  = tid >> 8;           // pair half
    const int lt   = tid & 255;          // scalar position in tile
    const int warp = mc;
    const int lane = ms;

    auto issue = [&](int t) {
        const int stage = t % STAGES;
        const float4* gp = reinterpret_cast<const float4*>(src + t * TILE) + 2 * ms;
        float* sp = &s_buf[stage * STAGE_FLOATS + mc * TILE] + 8 * ms;
        unsigned sa = (unsigned)__cvta_generic_to_shared(sp);
        asm volatile("cp.async.cg.shared.global [%0], [%1], 16;\n"
                     :: "r"(sa), "l"(gp) : "memory");
        asm volatile("cp.async.cg.shared.global [%0], [%1], 16;\n"
                     :: "r"(sa + 16), "l"(gp + 1) : "memory");
        asm volatile("cp.async.commit_group;" ::: "memory");
    };

    float acc[60];
    #pragma unroll
    for (int p = 0; p < 60; p++) acc[p] = 0.0f;

    // prologue: DEPTH tiles in flight
    #pragma unroll
    for (int t = 0; t < DEPTH; t++) issue(t);

    for (int t = 0; t < NT; t++) {
        asm volatile("cp.async.wait_group %0;" :: "n"(DEPTH - 1) : "memory");
        __syncthreads();                 // tile t visible; stage (t+DEPTH)%S free

        const float* sm = &s_buf[(t % STAGES) * STAGE_FLOATS];
        float v[NC];
        #pragma unroll
        for (int c = 0; c < NC; c++) v[c] = sm[c * TILE + lt];

        if (grp == 0) do_pairs<0 >(v, acc);
        else          do_pairs<60>(v, acc);

        if (t + DEPTH < NT) issue(t + DEPTH);
    }

    asm volatile("cp.async.wait_group 0;" ::: "memory");
    __syncthreads();

    // cross-warp reduce: butterfly -> smem partials [16 warps][60]
    float* s_part = s_buf;
    #pragma unroll
    for (int p = 0; p < 60; p++) {
        float vv = acc[p];
        vv += __shfl_xor_sync(0xffffffffu, vv, 16);
        vv += __shfl_xor_sync(0xffffffffu, vv, 8);
        vv += __shfl_xor_sync(0xffffffffu, vv, 4);
        vv += __shfl_xor_sync(0xffffffffu, vv, 2);
        vv += __shfl_xor_sync(0xffffffffu, vv, 1);
        if (lane == 0) s_part[warp * 60 + p] = vv;
    }
    __syncthreads();

    // pair-half h used warps [h*8, h*8+8)
    if (tid < NPAIR) {
        const int h  = tid / 60;
        const int pp = tid % 60;
        float s = 0.0f;
        #pragma unroll
        for (int w = 0; w < 8; w++) s += s_part[(h * 8 + w) * 60 + pp];
        g_S4[bg][q][tid] = s;
    }
}

// ---------------------------------------------------------------------------
// Kernel C: weighted |cov| reduction + margin + clamp + batch mean.
// 1 block, 1024 threads: (bg = tid>>2, quarter-slice qs = tid&3 over pairs).
// ---------------------------------------------------------------------------
__global__ void finalize_kernel(float* __restrict__ out) {
    __shared__ float red[NBG];
    const int tid = threadIdx.x;
    const int bgi = tid >> 2;            // 0..255
    const int qs  = tid & 3;             // pair slice
    const int g   = bgi & 31;

    float w[NC];
    #pragma unroll
    for (int c = 0; c < NC; c++) w[c] = g_wgt[g][c];

    const int p0 = qs * 30;
    float val = 0.0f;
    int p = 0;
    #pragma unroll
    for (int c = 0; c < NC; c++) {
        #pragma unroll
        for (int d = c + 1; d < NC; d++) {
            if (p >= p0 && p < p0 + 30) {
                const float S = g_S4[bgi][0][p] + g_S4[bgi][1][p] +
                                g_S4[bgi][2][p] + g_S4[bgi][3][p];
                val += w[c] * w[d] * fabsf(S);
            }
            p++;
        }
    }
    val += __shfl_xor_sync(0xffffffffu, val, 1);
    val += __shfl_xor_sync(0xffffffffu, val, 2);

    if (qs == 0) {
        const float sum_abs_cov = val / (float)(HW - 1);
        const float off_diag    = sum_abs_cov - 60.0f;   // margin = floor(120/2)
        red[bgi] = fmaxf(off_diag / 120.0f, 0.0f);
    }
    __syncthreads();

    for (int s = 128; s > 0; s >>= 1) {
        if (tid < s) red[tid] += red[tid + s];
        __syncthreads();
    }
    if (tid == 0) out[0] = red[0] / (float)NB;
}

// ---------------------------------------------------------------------------
extern "C" void kernel_launch(void* const* d_in, const int* in_sizes, int n_in,
                              void* d_out, int out_size) {
    (void)in_sizes; (void)n_in; (void)out_size;
    const float* x  = (const float*)d_in[0];   // [8,512,128,128] fp32
    const float* cw = (const float*)d_in[1];   // [19,512] fp32

    static int smem_set = 0;
    if (!smem_set) {
        cudaFuncSetAttribute(gram_kernel,
                             cudaFuncAttributeMaxDynamicSharedMemorySize,
                             SMEM_BYTES);
        smem_set = 1;
    }

    select_kernel<<<dim3(16, 8), 512>>>(cw);
    gram_kernel<<<1024, 512, SMEM_BYTES>>>(x);
    finalize_kernel<<<1, 1024>>>((float*)d_out);
}